// round 2
// baseline (speedup 1.0000x reference)
#include <cuda_runtime.h>
#include <cuda_bf16.h>

#define B_TOT 32768
#define T_LEN 200
#define DE    6
#define NIV   8
#define H     128
#define DIN   46
#define NPAIR (B_TOT/2)
#define ROWF  36   // floats per hidden-unit row in smem (14 dup weights + alpha,beta,gamma,c2 dup)

typedef unsigned long long ull;

static __device__ __forceinline__ ull pk2(float lo, float hi) {
    ull r; asm("mov.b64 %0,{%1,%2};" : "=l"(r) : "f"(lo), "f"(hi)); return r;
}
static __device__ __forceinline__ void upk2(ull v, float& lo, float& hi) {
    asm("mov.b64 {%0,%1},%2;" : "=f"(lo), "=f"(hi) : "l"(v));
}
static __device__ __forceinline__ ull fma2(ull a, ull b, ull c) {
    ull d; asm("fma.rn.f32x2 %0,%1,%2,%3;" : "=l"(d) : "l"(a), "l"(b), "l"(c)); return d;
}
static __device__ __forceinline__ ull mul2(ull a, ull b) {
    ull d; asm("mul.rn.f32x2 %0,%1,%2;" : "=l"(d) : "l"(a), "l"(b)); return d;
}
static __device__ __forceinline__ ull add2(ull a, ull b) {
    ull d; asm("add.rn.f32x2 %0,%1,%2;" : "=l"(d) : "l"(a), "l"(b)); return d;
}
static __device__ __forceinline__ ull relu2(ull a) {
    float lo, hi; upk2(a, lo, hi);
    lo = fmaxf(lo, 0.f); hi = fmaxf(hi, 0.f);
    return pk2(lo, hi);
}

// Fused forward+gradient MLP over H=128 hidden units.
// s: smem rows [w0d..w13d | alpha_d beta_d gamma_d c2_d], weights duplicated pairs.
// in6: 6 packed inputs (cols 0..5), in8: 8 packed inputs (cols 6..13).
// acc: 14 packed accumulators, caller-initialized; accumulates sum_h r'[h]*w[h][j].
static __device__ __forceinline__ void mlp_grad(const float* __restrict__ s,
                                                const ull* __restrict__ in6,
                                                const ull* __restrict__ in8,
                                                ull Epk, ull nupk, ull* acc)
{
#pragma unroll 2
    for (int h = 0; h < H; ++h) {
        const ulonglong2* r = reinterpret_cast<const ulonglong2*>(s + h * ROWF);
        ulonglong2 q0 = r[0], q1 = r[1], q2 = r[2], q3 = r[3], q4 = r[4];
        ulonglong2 q5 = r[5], q6 = r[6], q7 = r[7], q8 = r[8];
        // q7.x=alpha q7.y=beta q8.x=gamma q8.y=2*c2
        ull pa = fma2(q7.y, Epk, q7.x);
        pa = fma2(q8.x, nupk, pa);
        pa = fma2(q0.x, in6[0], pa);
        pa = fma2(q0.y, in6[1], pa);
        pa = fma2(q1.x, in6[2], pa);
        pa = fma2(q1.y, in6[3], pa);
        pa = fma2(q2.x, in6[4], pa);
        pa = fma2(q2.y, in6[5], pa);
        ull pb = mul2(q3.x, in8[0]);
        pb = fma2(q3.y, in8[1], pb);
        pb = fma2(q4.x, in8[2], pb);
        pb = fma2(q4.y, in8[3], pb);
        pb = fma2(q5.x, in8[4], pb);
        pb = fma2(q5.y, in8[5], pb);
        pb = fma2(q6.x, in8[6], pb);
        pb = fma2(q6.y, in8[7], pb);
        ull rr = mul2(relu2(add2(pa, pb)), q8.y);
        acc[0]  = fma2(q0.x, rr, acc[0]);
        acc[1]  = fma2(q0.y, rr, acc[1]);
        acc[2]  = fma2(q1.x, rr, acc[2]);
        acc[3]  = fma2(q1.y, rr, acc[3]);
        acc[4]  = fma2(q2.x, rr, acc[4]);
        acc[5]  = fma2(q2.y, rr, acc[5]);
        acc[6]  = fma2(q3.x, rr, acc[6]);
        acc[7]  = fma2(q3.y, rr, acc[7]);
        acc[8]  = fma2(q4.x, rr, acc[8]);
        acc[9]  = fma2(q4.y, rr, acc[9]);
        acc[10] = fma2(q5.x, rr, acc[10]);
        acc[11] = fma2(q5.y, rr, acc[11]);
        acc[12] = fma2(q6.x, rr, acc[12]);
        acc[13] = fma2(q6.y, rr, acc[13]);
    }
}

__global__ void __launch_bounds__(128, 1) visco_kernel(
    const float* __restrict__ e,   const float* __restrict__ edot,
    const float* __restrict__ Eg,  const float* __restrict__ nug,
    const float* __restrict__ We1, const float* __restrict__ be1,
    const float* __restrict__ We2,
    const float* __restrict__ Wd1, const float* __restrict__ bd1,
    const float* __restrict__ Wd2,
    const float* __restrict__ WE,  const float* __restrict__ bE,
    const float* __restrict__ Wnu, const float* __restrict__ bnu,
    float* __restrict__ out)
{
    __shared__ __align__(16) float sE[H * ROWF];
    __shared__ __align__(16) float sD[H * ROWF];

    // ---- build derived weight tables in smem (one h per thread) ----
    {
        int h = threadIdx.x;
        const float* w1 = We1 + h * DIN;
#pragma unroll
        for (int j = 0; j < 14; ++j) { float w = w1[j]; sE[h*ROWF + 2*j] = w; sE[h*ROWF + 2*j + 1] = w; }
        float a = be1[h], bt = 0.f, gm = 0.f;
#pragma unroll
        for (int k = 0; k < 16; ++k) { float wm = w1[14 + k]; a += wm * bE[k];  bt += wm * WE[k]; }
#pragma unroll
        for (int k = 0; k < 16; ++k) { float wm = w1[30 + k]; a += wm * bnu[k]; gm += wm * Wnu[k]; }
        sE[h*ROWF + 28] = a;  sE[h*ROWF + 29] = a;
        sE[h*ROWF + 30] = bt; sE[h*ROWF + 31] = bt;
        sE[h*ROWF + 32] = gm; sE[h*ROWF + 33] = gm;
        float c2 = 2.f * (We2[h] + We2[H + h]);
        sE[h*ROWF + 34] = c2; sE[h*ROWF + 35] = c2;

        const float* w2 = Wd1 + h * DIN;
#pragma unroll
        for (int j = 0; j < 14; ++j) { float w = -w2[j]; sD[h*ROWF + 2*j] = w; sD[h*ROWF + 2*j + 1] = w; }
        a = bd1[h]; bt = 0.f; gm = 0.f;
#pragma unroll
        for (int k = 0; k < 16; ++k) { float wm = w2[14 + k]; a += wm * bE[k];  bt += wm * WE[k]; }
#pragma unroll
        for (int k = 0; k < 16; ++k) { float wm = w2[30 + k]; a += wm * bnu[k]; gm += wm * Wnu[k]; }
        sD[h*ROWF + 28] = a;  sD[h*ROWF + 29] = a;
        sD[h*ROWF + 30] = bt; sD[h*ROWF + 31] = bt;
        sD[h*ROWF + 32] = gm; sD[h*ROWF + 33] = gm;
        c2 = 2.f * Wd2[h];
        sD[h*ROWF + 34] = c2; sD[h*ROWF + 35] = c2;
    }
    __syncthreads();

    int p = blockIdx.x * blockDim.x + threadIdx.x;
    if (p >= NPAIR) return;
    size_t b0 = 2 * (size_t)p, b1 = b0 + 1;

    ull Epk  = pk2(Eg[b0],  Eg[b1]);
    ull nupk = pk2(nug[b0], nug[b1]);

    const float* e0 = e    + b0 * T_LEN * DE;
    const float* e1 = e    + b1 * T_LEN * DE;
    const float* d0 = edot + b0 * T_LEN * DE;
    const float* d1 = edot + b1 * T_LEN * DE;
    float* so0 = out + b0 * T_LEN * DE;   // stress region
    float* so1 = out + b1 * T_LEN * DE;
    float* xo0 = out + (size_t)B_TOT * T_LEN * DE + b0 * T_LEN * NIV;  // xi region
    float* xo1 = out + (size_t)B_TOT * T_LEN * DE + b1 * T_LEN * NIV;

    ull xi[NIV];
#pragma unroll
    for (int j = 0; j < NIV; ++j) xi[j] = 0ULL;   // two packed +0.0f

    const ull NDT = pk2(-0.01f, -0.01f);
    const ull SGN = 0x8000000080000000ULL;

    // prefetch t=0 (addresses are 8B aligned: stride 24B)
    float2 ea0 = *(const float2*)(e0),     ea1 = *(const float2*)(e0 + 2), ea2 = *(const float2*)(e0 + 4);
    float2 eb0 = *(const float2*)(e1),     eb1 = *(const float2*)(e1 + 2), eb2 = *(const float2*)(e1 + 4);
    float2 da0 = *(const float2*)(d0),     da1 = *(const float2*)(d0 + 2), da2 = *(const float2*)(d0 + 4);
    float2 db0 = *(const float2*)(d1),     db1 = *(const float2*)(d1 + 2), db2 = *(const float2*)(d1 + 4);

    for (int t = 0; t < T_LEN; ++t) {
        // pack current inputs
        ull et[6]  = { pk2(ea0.x, eb0.x), pk2(ea0.y, eb0.y), pk2(ea1.x, eb1.x),
                       pk2(ea1.y, eb1.y), pk2(ea2.x, eb2.x), pk2(ea2.y, eb2.y) };
        ull edn[6] = { pk2(da0.x, db0.x) ^ SGN, pk2(da0.y, db0.y) ^ SGN, pk2(da1.x, db1.x) ^ SGN,
                       pk2(da1.y, db1.y) ^ SGN, pk2(da2.x, db2.x) ^ SGN, pk2(da2.y, db2.y) ^ SGN };

        // prefetch next step while computing this one
        if (t + 1 < T_LEN) {
            int o = (t + 1) * DE;
            ea0 = *(const float2*)(e0 + o); ea1 = *(const float2*)(e0 + o + 2); ea2 = *(const float2*)(e0 + o + 4);
            eb0 = *(const float2*)(e1 + o); eb1 = *(const float2*)(e1 + o + 2); eb2 = *(const float2*)(e1 + o + 4);
            da0 = *(const float2*)(d0 + o); da1 = *(const float2*)(d0 + o + 2); da2 = *(const float2*)(d0 + o + 4);
            db0 = *(const float2*)(d1 + o); db1 = *(const float2*)(d1 + o + 2); db2 = *(const float2*)(d1 + o + 4);
        }

        // write xi output (value entering this step)
        {
            size_t ox = (size_t)t * NIV;
#pragma unroll
            for (int j = 0; j < NIV; ++j) {
                float lo, hi; upk2(xi[j], lo, hi);
                xo0[ox + j] = lo; xo1[ox + j] = hi;
            }
        }

        // E-MLP: acc = (2 r c) @ We1[:, :14];  [0:6]=s_eq, [6:14]=d
        ull accE[14];
#pragma unroll
        for (int j = 0; j < 14; ++j) accE[j] = 0ULL;
        mlp_grad(sE, et, xi, Epk, nupk, accE);

        // D-MLP with negated weights; init cols 0..5 with s_eq so acc = stress directly.
        ull accD[14];
#pragma unroll
        for (int j = 0; j < 6; ++j) accD[j] = accE[j];
#pragma unroll
        for (int j = 6; j < 14; ++j) accD[j] = 0ULL;
        mlp_grad(sD, edn, accE + 6, Epk, nupk, accD);

        // stress out
        {
            size_t os = (size_t)t * DE;
#pragma unroll
            for (int j = 0; j < DE; ++j) {
                float lo, hi; upk2(accD[j], lo, hi);
                so0[os + j] = lo; so1[os + j] = hi;
            }
        }
        // xi += DT * kinetics   (accD[6+j] = -kinetics, NDT = -DT)
#pragma unroll
        for (int j = 0; j < NIV; ++j) xi[j] = fma2(accD[6 + j], NDT, xi[j]);
    }
}

extern "C" void kernel_launch(void* const* d_in, const int* in_sizes, int n_in,
                              void* d_out, int out_size) {
    const float* e    = (const float*)d_in[0];
    const float* edot = (const float*)d_in[1];
    const float* Eg   = (const float*)d_in[2];
    const float* nug  = (const float*)d_in[3];
    const float* We1  = (const float*)d_in[4];
    const float* be1  = (const float*)d_in[5];
    const float* We2  = (const float*)d_in[6];
    // d_in[7] = be2 (unused by gradient)
    const float* Wd1  = (const float*)d_in[8];
    const float* bd1  = (const float*)d_in[9];
    const float* Wd2  = (const float*)d_in[10];
    // d_in[11] = bd2 (unused)
    const float* WE   = (const float*)d_in[12];
    const float* bE   = (const float*)d_in[13];
    const float* Wnu  = (const float*)d_in[14];
    const float* bnu  = (const float*)d_in[15];
    float* out = (float*)d_out;

    visco_kernel<<<NPAIR / 128, 128>>>(e, edot, Eg, nug, We1, be1, We2,
                                       Wd1, bd1, Wd2, WE, bE, Wnu, bnu, out);
}

// round 3
// speedup vs baseline: 1.1967x; 1.1967x over previous
#include <cuda_runtime.h>
#include <cuda_bf16.h>

#define B_TOT 32768
#define T_LEN 200
#define DE    6
#define NIV   8
#define H     128
#define DIN   46
#define NPAIR (B_TOT/2)
#define ROWF  36   // floats per hidden-unit row in smem (14 dup weights + alpha,beta,gamma,c2 dup)
#define HSPLIT 2
#define HHALF (H/HSPLIT)

typedef unsigned long long ull;

static __device__ __forceinline__ ull pk2(float lo, float hi) {
    ull r; asm("mov.b64 %0,{%1,%2};" : "=l"(r) : "f"(lo), "f"(hi)); return r;
}
static __device__ __forceinline__ void upk2(ull v, float& lo, float& hi) {
    asm("mov.b64 {%0,%1},%2;" : "=f"(lo), "=f"(hi) : "l"(v));
}
static __device__ __forceinline__ ull fma2(ull a, ull b, ull c) {
    ull d; asm("fma.rn.f32x2 %0,%1,%2,%3;" : "=l"(d) : "l"(a), "l"(b), "l"(c)); return d;
}
static __device__ __forceinline__ ull mul2(ull a, ull b) {
    ull d; asm("mul.rn.f32x2 %0,%1,%2;" : "=l"(d) : "l"(a), "l"(b)); return d;
}
static __device__ __forceinline__ ull add2(ull a, ull b) {
    ull d; asm("add.rn.f32x2 %0,%1,%2;" : "=l"(d) : "l"(a), "l"(b)); return d;
}
static __device__ __forceinline__ ull relu2(ull a) {
    float lo, hi; upk2(a, lo, hi);
    lo = fmaxf(lo, 0.f); hi = fmaxf(hi, 0.f);
    return pk2(lo, hi);
}
// combine packed accumulator with h-split partner (lane ^ 16)
static __device__ __forceinline__ ull bfly16(ull v) {
    return __shfl_xor_sync(0xFFFFFFFFu, v, 16);
}

// Fused forward+gradient MLP over HHALF hidden units starting at hbase.
static __device__ __forceinline__ void mlp_grad(const float* __restrict__ s,
                                                int hbase,
                                                const ull* __restrict__ in6,
                                                const ull* __restrict__ in8,
                                                ull Epk, ull nupk, ull* acc)
{
    const float* sbase = s + hbase * ROWF;
#pragma unroll 2
    for (int h = 0; h < HHALF; ++h) {
        const ulonglong2* r = reinterpret_cast<const ulonglong2*>(sbase + h * ROWF);
        ulonglong2 q0 = r[0], q1 = r[1], q2 = r[2], q3 = r[3], q4 = r[4];
        ulonglong2 q5 = r[5], q6 = r[6], q7 = r[7], q8 = r[8];
        // q7.x=alpha q7.y=beta q8.x=gamma q8.y=2*c
        ull pa = fma2(q7.y, Epk, q7.x);
        pa = fma2(q8.x, nupk, pa);
        pa = fma2(q0.x, in6[0], pa);
        pa = fma2(q0.y, in6[1], pa);
        pa = fma2(q1.x, in6[2], pa);
        pa = fma2(q1.y, in6[3], pa);
        pa = fma2(q2.x, in6[4], pa);
        pa = fma2(q2.y, in6[5], pa);
        ull pb = mul2(q3.x, in8[0]);
        pb = fma2(q3.y, in8[1], pb);
        pb = fma2(q4.x, in8[2], pb);
        pb = fma2(q4.y, in8[3], pb);
        pb = fma2(q5.x, in8[4], pb);
        pb = fma2(q5.y, in8[5], pb);
        pb = fma2(q6.x, in8[6], pb);
        pb = fma2(q6.y, in8[7], pb);
        ull rr = mul2(relu2(add2(pa, pb)), q8.y);
        acc[0]  = fma2(q0.x, rr, acc[0]);
        acc[1]  = fma2(q0.y, rr, acc[1]);
        acc[2]  = fma2(q1.x, rr, acc[2]);
        acc[3]  = fma2(q1.y, rr, acc[3]);
        acc[4]  = fma2(q2.x, rr, acc[4]);
        acc[5]  = fma2(q2.y, rr, acc[5]);
        acc[6]  = fma2(q3.x, rr, acc[6]);
        acc[7]  = fma2(q3.y, rr, acc[7]);
        acc[8]  = fma2(q4.x, rr, acc[8]);
        acc[9]  = fma2(q4.y, rr, acc[9]);
        acc[10] = fma2(q5.x, rr, acc[10]);
        acc[11] = fma2(q5.y, rr, acc[11]);
        acc[12] = fma2(q6.x, rr, acc[12]);
        acc[13] = fma2(q6.y, rr, acc[13]);
    }
}

__global__ void __launch_bounds__(128, 2) visco_kernel(
    const float* __restrict__ e,   const float* __restrict__ edot,
    const float* __restrict__ Eg,  const float* __restrict__ nug,
    const float* __restrict__ We1, const float* __restrict__ be1,
    const float* __restrict__ We2,
    const float* __restrict__ Wd1, const float* __restrict__ bd1,
    const float* __restrict__ Wd2,
    const float* __restrict__ WE,  const float* __restrict__ bE,
    const float* __restrict__ Wnu, const float* __restrict__ bnu,
    float* __restrict__ out)
{
    __shared__ __align__(16) float sE[H * ROWF];
    __shared__ __align__(16) float sD[H * ROWF];

    // ---- build derived weight tables in smem (one h per thread) ----
    {
        int h = threadIdx.x;
        const float* w1 = We1 + h * DIN;
#pragma unroll
        for (int j = 0; j < 14; ++j) { float w = w1[j]; sE[h*ROWF + 2*j] = w; sE[h*ROWF + 2*j + 1] = w; }
        float a = be1[h], bt = 0.f, gm = 0.f;
#pragma unroll
        for (int k = 0; k < 16; ++k) { float wm = w1[14 + k]; a += wm * bE[k];  bt += wm * WE[k]; }
#pragma unroll
        for (int k = 0; k < 16; ++k) { float wm = w1[30 + k]; a += wm * bnu[k]; gm += wm * Wnu[k]; }
        sE[h*ROWF + 28] = a;  sE[h*ROWF + 29] = a;
        sE[h*ROWF + 30] = bt; sE[h*ROWF + 31] = bt;
        sE[h*ROWF + 32] = gm; sE[h*ROWF + 33] = gm;
        float c2 = 2.f * (We2[h] + We2[H + h]);
        sE[h*ROWF + 34] = c2; sE[h*ROWF + 35] = c2;

        const float* w2 = Wd1 + h * DIN;
#pragma unroll
        for (int j = 0; j < 14; ++j) { float w = -w2[j]; sD[h*ROWF + 2*j] = w; sD[h*ROWF + 2*j + 1] = w; }
        a = bd1[h]; bt = 0.f; gm = 0.f;
#pragma unroll
        for (int k = 0; k < 16; ++k) { float wm = w2[14 + k]; a += wm * bE[k];  bt += wm * WE[k]; }
#pragma unroll
        for (int k = 0; k < 16; ++k) { float wm = w2[30 + k]; a += wm * bnu[k]; gm += wm * Wnu[k]; }
        sD[h*ROWF + 28] = a;  sD[h*ROWF + 29] = a;
        sD[h*ROWF + 30] = bt; sD[h*ROWF + 31] = bt;
        sD[h*ROWF + 32] = gm; sD[h*ROWF + 33] = gm;
        c2 = 2.f * Wd2[h];
        sD[h*ROWF + 34] = c2; sD[h*ROWF + 35] = c2;
    }
    __syncthreads();

    // Thread mapping: warp w, lane l. s = l>>4 selects the h-half; pair index
    // pairs threads (lane, lane^16) on the same pair. 64 pairs per block.
    int lane = threadIdx.x & 31;
    int wrp  = threadIdx.x >> 5;
    int s    = lane >> 4;
    int hbase = s * HHALF;
    int p = blockIdx.x * 64 + wrp * 16 + (lane & 15);
    size_t b0 = 2 * (size_t)p, b1 = b0 + 1;

    ull Epk  = pk2(Eg[b0],  Eg[b1]);
    ull nupk = pk2(nug[b0], nug[b1]);

    const float* e0 = e    + b0 * T_LEN * DE;
    const float* e1 = e    + b1 * T_LEN * DE;
    const float* d0 = edot + b0 * T_LEN * DE;
    const float* d1 = edot + b1 * T_LEN * DE;
    float* so0 = out + b0 * T_LEN * DE;   // stress region
    float* so1 = out + b1 * T_LEN * DE;
    float* xo0 = out + (size_t)B_TOT * T_LEN * DE + b0 * T_LEN * NIV;  // xi region
    float* xo1 = out + (size_t)B_TOT * T_LEN * DE + b1 * T_LEN * NIV;

    ull xi[NIV];
#pragma unroll
    for (int j = 0; j < NIV; ++j) xi[j] = 0ULL;

    const ull NDT = pk2(-0.01f, -0.01f);
    const ull SGN = 0x8000000080000000ULL;

    // prefetch t=0
    float2 ea0 = *(const float2*)(e0), ea1 = *(const float2*)(e0 + 2), ea2 = *(const float2*)(e0 + 4);
    float2 eb0 = *(const float2*)(e1), eb1 = *(const float2*)(e1 + 2), eb2 = *(const float2*)(e1 + 4);
    float2 da0 = *(const float2*)(d0), da1 = *(const float2*)(d0 + 2), da2 = *(const float2*)(d0 + 4);
    float2 db0 = *(const float2*)(d1), db1 = *(const float2*)(d1 + 2), db2 = *(const float2*)(d1 + 4);

    for (int t = 0; t < T_LEN; ++t) {
        ull et[6]  = { pk2(ea0.x, eb0.x), pk2(ea0.y, eb0.y), pk2(ea1.x, eb1.x),
                       pk2(ea1.y, eb1.y), pk2(ea2.x, eb2.x), pk2(ea2.y, eb2.y) };
        ull edn[6] = { pk2(da0.x, db0.x) ^ SGN, pk2(da0.y, db0.y) ^ SGN, pk2(da1.x, db1.x) ^ SGN,
                       pk2(da1.y, db1.y) ^ SGN, pk2(da2.x, db2.x) ^ SGN, pk2(da2.y, db2.y) ^ SGN };

        if (t + 1 < T_LEN) {
            int o = (t + 1) * DE;
            ea0 = *(const float2*)(e0 + o); ea1 = *(const float2*)(e0 + o + 2); ea2 = *(const float2*)(e0 + o + 4);
            eb0 = *(const float2*)(e1 + o); eb1 = *(const float2*)(e1 + o + 2); eb2 = *(const float2*)(e1 + o + 4);
            da0 = *(const float2*)(d0 + o); da1 = *(const float2*)(d0 + o + 2); da2 = *(const float2*)(d0 + o + 4);
            db0 = *(const float2*)(d1 + o); db1 = *(const float2*)(d1 + o + 2); db2 = *(const float2*)(d1 + o + 4);
        }

        // xi output (value entering this step) — s==1 thread stores
        if (s) {
            size_t ox = (size_t)t * NIV;
#pragma unroll
            for (int j = 0; j < NIV; ++j) {
                float lo, hi; upk2(xi[j], lo, hi);
                xo0[ox + j] = lo; xo1[ox + j] = hi;
            }
        }

        // E-MLP over this thread's h-half, then butterfly-combine with partner
        ull accE[14];
#pragma unroll
        for (int j = 0; j < 14; ++j) accE[j] = 0ULL;
        mlp_grad(sE, hbase, et, xi, Epk, nupk, accE);
#pragma unroll
        for (int j = 0; j < 14; ++j) accE[j] = add2(accE[j], bfly16(accE[j]));
        // accE[0:6] = s_eq (full), accE[6:14] = d (full)

        // D-MLP (negated weights): accumulates -s_neq / -kinetics over h-half
        ull accD[14];
#pragma unroll
        for (int j = 0; j < 14; ++j) accD[j] = 0ULL;
        mlp_grad(sD, hbase, edn, accE + 6, Epk, nupk, accD);
#pragma unroll
        for (int j = 0; j < 14; ++j) accD[j] = add2(accD[j], bfly16(accD[j]));

        // stress = s_eq + (-s_neq) — s==0 thread stores
        if (!s) {
            size_t os = (size_t)t * DE;
#pragma unroll
            for (int j = 0; j < DE; ++j) {
                float lo, hi; upk2(add2(accE[j], accD[j]), lo, hi);
                so0[os + j] = lo; so1[os + j] = hi;
            }
        }
        // xi += DT * kinetics  (accD[6+j] = -kinetics, NDT = -DT); both threads update
#pragma unroll
        for (int j = 0; j < NIV; ++j) xi[j] = fma2(accD[6 + j], NDT, xi[j]);
    }
}

extern "C" void kernel_launch(void* const* d_in, const int* in_sizes, int n_in,
                              void* d_out, int out_size) {
    const float* e    = (const float*)d_in[0];
    const float* edot = (const float*)d_in[1];
    const float* Eg   = (const float*)d_in[2];
    const float* nug  = (const float*)d_in[3];
    const float* We1  = (const float*)d_in[4];
    const float* be1  = (const float*)d_in[5];
    const float* We2  = (const float*)d_in[6];
    const float* Wd1  = (const float*)d_in[8];
    const float* bd1  = (const float*)d_in[9];
    const float* Wd2  = (const float*)d_in[10];
    const float* WE   = (const float*)d_in[12];
    const float* bE   = (const float*)d_in[13];
    const float* Wnu  = (const float*)d_in[14];
    const float* bnu  = (const float*)d_in[15];
    float* out = (float*)d_out;

    visco_kernel<<<NPAIR / 64, 128>>>(e, edot, Eg, nug, We1, be1, We2,
                                      Wd1, bd1, Wd2, WE, bE, Wnu, bnu, out);
}

// round 4
// speedup vs baseline: 1.4378x; 1.2014x over previous
#include <cuda_runtime.h>
#include <cuda_bf16.h>

#define B_TOT 32768
#define T_LEN 200
#define DE    6
#define NIV   8
#define H     128
#define DIN   46
#define NPAIR (B_TOT/2)
#define UNITS 64
#define ROWF  36
#define GRP   4
#define UPG   16
#define TD    (T_LEN*DE)

typedef unsigned long long ull;

static __device__ __forceinline__ ull pk2(float lo, float hi) {
    ull r; asm("mov.b64 %0,{%1,%2};" : "=l"(r) : "f"(lo), "f"(hi)); return r;
}
static __device__ __forceinline__ void upk2(ull v, float& lo, float& hi) {
    asm("mov.b64 {%0,%1},%2;" : "=f"(lo), "=f"(hi) : "l"(v));
}
static __device__ __forceinline__ ull fma2(ull a, ull b, ull c) {
    ull d; asm("fma.rn.f32x2 %0,%1,%2,%3;" : "=l"(d) : "l"(a), "l"(b), "l"(c)); return d;
}
static __device__ __forceinline__ ull mul2(ull a, ull b) {
    ull d; asm("mul.rn.f32x2 %0,%1,%2;" : "=l"(d) : "l"(a), "l"(b)); return d;
}
static __device__ __forceinline__ ull add2(ull a, ull b) {
    ull d; asm("add.rn.f32x2 %0,%1,%2;" : "=l"(d) : "l"(a), "l"(b)); return d;
}
static __device__ __forceinline__ ull relu2(ull a) {
    float lo, hi; upk2(a, lo, hi);
    lo = fmaxf(lo, 0.f); hi = fmaxf(hi, 0.f);
    return pk2(lo, hi);
}
static __device__ __forceinline__ ull dupf(float v) { return pk2(v, v); }

static __device__ __forceinline__ float red4(ull acc) {
    float lo, hi; upk2(acc, lo, hi);
    float s = lo + hi;
    s += __shfl_xor_sync(0xFFFFFFFFu, s, 8);
    s += __shfl_xor_sync(0xFFFFFFFFu, s, 16);
    return s;
}

static __device__ __forceinline__ void mlp2(const float* __restrict__ tab, int g,
    const ull* __restrict__ i6a, const ull* __restrict__ i8a, ull Ea, ull nua,
    const ull* __restrict__ i6b, const ull* __restrict__ i8b, ull Eb, ull nub,
    ull* __restrict__ accA, ull* __restrict__ accB)
{
    const int base = g * UPG;
#pragma unroll 4
    for (int i = 0; i < UPG; ++i) {
        int uu = base + ((i + g) & (UPG - 1));   // stagger: conflict-free banks
        const ulonglong2* r = reinterpret_cast<const ulonglong2*>(tab + uu * ROWF);
        ulonglong2 r0 = r[0], r1 = r[1], r2 = r[2], r3 = r[3], r4 = r[4];
        ulonglong2 r5 = r[5], r6 = r[6], r7 = r[7], r8 = r[8];

        ull pa = fma2(r7.y, Ea, r7.x);  pa = fma2(r8.x, nua, pa);
        pa = fma2(r0.x, i6a[0], pa);    pa = fma2(r0.y, i6a[1], pa);
        pa = fma2(r1.x, i6a[2], pa);    pa = fma2(r1.y, i6a[3], pa);
        pa = fma2(r2.x, i6a[4], pa);    pa = fma2(r2.y, i6a[5], pa);
        ull qa = mul2(r3.x, i8a[0]);    qa = fma2(r3.y, i8a[1], qa);
        qa = fma2(r4.x, i8a[2], qa);    qa = fma2(r4.y, i8a[3], qa);
        qa = fma2(r5.x, i8a[4], qa);    qa = fma2(r5.y, i8a[5], qa);
        qa = fma2(r6.x, i8a[6], qa);    qa = fma2(r6.y, i8a[7], qa);
        ull ra = mul2(relu2(add2(pa, qa)), r8.y);

        ull pb = fma2(r7.y, Eb, r7.x);  pb = fma2(r8.x, nub, pb);
        pb = fma2(r0.x, i6b[0], pb);    pb = fma2(r0.y, i6b[1], pb);
        pb = fma2(r1.x, i6b[2], pb);    pb = fma2(r1.y, i6b[3], pb);
        pb = fma2(r2.x, i6b[4], pb);    pb = fma2(r2.y, i6b[5], pb);
        ull qb = mul2(r3.x, i8b[0]);    qb = fma2(r3.y, i8b[1], qb);
        qb = fma2(r4.x, i8b[2], qb);    qb = fma2(r4.y, i8b[3], qb);
        qb = fma2(r5.x, i8b[4], qb);    qb = fma2(r5.y, i8b[5], qb);
        qb = fma2(r6.x, i8b[6], qb);    qb = fma2(r6.y, i8b[7], qb);
        ull rb = mul2(relu2(add2(pb, qb)), r8.y);

        accA[0]  = fma2(r0.x, ra, accA[0]);   accB[0]  = fma2(r0.x, rb, accB[0]);
        accA[1]  = fma2(r0.y, ra, accA[1]);   accB[1]  = fma2(r0.y, rb, accB[1]);
        accA[2]  = fma2(r1.x, ra, accA[2]);   accB[2]  = fma2(r1.x, rb, accB[2]);
        accA[3]  = fma2(r1.y, ra, accA[3]);   accB[3]  = fma2(r1.y, rb, accB[3]);
        accA[4]  = fma2(r2.x, ra, accA[4]);   accB[4]  = fma2(r2.x, rb, accB[4]);
        accA[5]  = fma2(r2.y, ra, accA[5]);   accB[5]  = fma2(r2.y, rb, accB[5]);
        accA[6]  = fma2(r3.x, ra, accA[6]);   accB[6]  = fma2(r3.x, rb, accB[6]);
        accA[7]  = fma2(r3.y, ra, accA[7]);   accB[7]  = fma2(r3.y, rb, accB[7]);
        accA[8]  = fma2(r4.x, ra, accA[8]);   accB[8]  = fma2(r4.x, rb, accB[8]);
        accA[9]  = fma2(r4.y, ra, accA[9]);   accB[9]  = fma2(r4.y, rb, accB[9]);
        accA[10] = fma2(r5.x, ra, accA[10]);  accB[10] = fma2(r5.x, rb, accB[10]);
        accA[11] = fma2(r5.y, ra, accA[11]);  accB[11] = fma2(r5.y, rb, accB[11]);
        accA[12] = fma2(r6.x, ra, accA[12]);  accB[12] = fma2(r6.x, rb, accB[12]);
        accA[13] = fma2(r6.y, ra, accA[13]);  accB[13] = fma2(r6.y, rb, accB[13]);
    }
}

__global__ void __launch_bounds__(128, 2) visco_kernel(
    const float* __restrict__ e,   const float* __restrict__ edot,
    const float* __restrict__ Eg,  const float* __restrict__ nug,
    const float* __restrict__ We1, const float* __restrict__ be1,
    const float* __restrict__ We2,
    const float* __restrict__ Wd1, const float* __restrict__ bd1,
    const float* __restrict__ Wd2,
    const float* __restrict__ WE,  const float* __restrict__ bE,
    const float* __restrict__ Wnu, const float* __restrict__ bnu,
    float* __restrict__ out)
{
    __shared__ __align__(16) float sE2[UNITS * ROWF];
    __shared__ __align__(16) float sD2[UNITS * ROWF];

    {
        int h = threadIdx.x;
        int u = h >> 1, par = h & 1;
        float* dE = sE2 + u * ROWF + par;
        float* dD = sD2 + u * ROWF + par;

        const float* w1 = We1 + h * DIN;
#pragma unroll
        for (int j = 0; j < 14; ++j) dE[2 * j] = w1[j];
        float a = be1[h], bt = 0.f, gm = 0.f;
#pragma unroll
        for (int k = 0; k < 16; ++k) { float wm = w1[14 + k]; a += wm * bE[k];  bt += wm * WE[k]; }
#pragma unroll
        for (int k = 0; k < 16; ++k) { float wm = w1[30 + k]; a += wm * bnu[k]; gm += wm * Wnu[k]; }
        dE[28] = a; dE[30] = bt; dE[32] = gm;
        dE[34] = 2.f * (We2[h] + We2[H + h]);

        const float* w2 = Wd1 + h * DIN;
#pragma unroll
        for (int j = 0; j < 14; ++j) dD[2 * j] = -w2[j];
        a = bd1[h]; bt = 0.f; gm = 0.f;
#pragma unroll
        for (int k = 0; k < 16; ++k) { float wm = w2[14 + k]; a += wm * bE[k];  bt += wm * WE[k]; }
#pragma unroll
        for (int k = 0; k < 16; ++k) { float wm = w2[30 + k]; a += wm * bnu[k]; gm += wm * Wnu[k]; }
        dD[28] = a; dD[30] = bt; dD[32] = gm;
        dD[34] = 2.f * Wd2[h];
    }
    __syncthreads();

    const int lane = threadIdx.x & 31;
    const int wrp  = threadIdx.x >> 5;
    const int pr   = lane & 7;
    const int g    = lane >> 3;
    const ull NDT2 = pk2(-0.01f, -0.01f);
    const ull SGN  = 0x8000000080000000ULL;

    for (int c = 0; c < 2; ++c) {
        int p = blockIdx.x * 64 + c * 32 + wrp * 8 + pr;
        size_t b0 = 2 * (size_t)p, b1 = b0 + 1;

        ull E0d  = dupf(Eg[b0]),  E1d  = dupf(Eg[b1]);
        ull nu0d = dupf(nug[b0]), nu1d = dupf(nug[b1]);

        const float* pe0 = e    + b0 * TD;
        const float* pe1 = pe0  + TD;
        const float* pd0 = edot + b0 * TD;
        const float* pd1 = pd0  + TD;
        float* so0 = out + b0 * TD;
        float* so1 = so0 + TD;
        float* xo0 = out + (size_t)B_TOT * TD + b0 * (size_t)(T_LEN * NIV);
        float* xo1 = xo0 + T_LEN * NIV;

        ull xi0[NIV], xi1[NIV];
#pragma unroll
        for (int j = 0; j < NIV; ++j) { xi0[j] = 0ULL; xi1[j] = 0ULL; }

        float2 ea0 = *(const float2*)(pe0), ea1 = *(const float2*)(pe0 + 2), ea2 = *(const float2*)(pe0 + 4);
        float2 eb0 = *(const float2*)(pe1), eb1 = *(const float2*)(pe1 + 2), eb2 = *(const float2*)(pe1 + 4);
        float2 da0 = *(const float2*)(pd0), da1 = *(const float2*)(pd0 + 2), da2 = *(const float2*)(pd0 + 4);
        float2 db0 = *(const float2*)(pd1), db1 = *(const float2*)(pd1 + 2), db2 = *(const float2*)(pd1 + 4);

        for (int t = 0; t < T_LEN; ++t) {
            ull et0[6] = { dupf(ea0.x), dupf(ea0.y), dupf(ea1.x), dupf(ea1.y), dupf(ea2.x), dupf(ea2.y) };
            ull et1[6] = { dupf(eb0.x), dupf(eb0.y), dupf(eb1.x), dupf(eb1.y), dupf(eb2.x), dupf(eb2.y) };
            ull ed0[6] = { dupf(da0.x) ^ SGN, dupf(da0.y) ^ SGN, dupf(da1.x) ^ SGN,
                           dupf(da1.y) ^ SGN, dupf(da2.x) ^ SGN, dupf(da2.y) ^ SGN };
            ull ed1[6] = { dupf(db0.x) ^ SGN, dupf(db0.y) ^ SGN, dupf(db1.x) ^ SGN,
                           dupf(db1.y) ^ SGN, dupf(db2.x) ^ SGN, dupf(db2.y) ^ SGN };

            if (t + 1 < T_LEN) {
                int o = (t + 1) * DE;
                ea0 = *(const float2*)(pe0 + o); ea1 = *(const float2*)(pe0 + o + 2); ea2 = *(const float2*)(pe0 + o + 4);
                eb0 = *(const float2*)(pe1 + o); eb1 = *(const float2*)(pe1 + o + 2); eb2 = *(const float2*)(pe1 + o + 4);
                da0 = *(const float2*)(pd0 + o); da1 = *(const float2*)(pd0 + o + 2); da2 = *(const float2*)(pd0 + o + 4);
                db0 = *(const float2*)(pd1 + o); db1 = *(const float2*)(pd1 + o + 2); db2 = *(const float2*)(pd1 + o + 4);
            }

            if (g == 1) {
                int ox = t * NIV;
#pragma unroll
                for (int k = 0; k < NIV; k += 2) {
                    float a0, z, a1;
                    upk2(xi0[k], a0, z); upk2(xi0[k + 1], a1, z);
                    *(float2*)(xo0 + ox + k) = make_float2(a0, a1);
                    upk2(xi1[k], a0, z); upk2(xi1[k + 1], a1, z);
                    *(float2*)(xo1 + ox + k) = make_float2(a0, a1);
                }
            }

            ull accA[14], accB[14];
#pragma unroll
            for (int j = 0; j < 14; ++j) { accA[j] = 0ULL; accB[j] = 0ULL; }
            mlp2(sE2, g, et0, xi0, E0d, nu0d, et1, xi1, E1d, nu1d, accA, accB);

            float seq0[6], seq1[6];
            ull d0[8], d1[8];
#pragma unroll
            for (int j = 0; j < 6; ++j) { seq0[j] = red4(accA[j]); seq1[j] = red4(accB[j]); }
#pragma unroll
            for (int j = 0; j < 8; ++j) { d0[j] = dupf(red4(accA[6 + j])); d1[j] = dupf(red4(accB[6 + j])); }

#pragma unroll
            for (int j = 0; j < 14; ++j) { accA[j] = 0ULL; accB[j] = 0ULL; }
            mlp2(sD2, g, ed0, d0, E0d, nu0d, ed1, d1, E1d, nu1d, accA, accB);

            // uniform reductions (all lanes participate), then divergent stores
            float st0[6], st1[6], kin0[8], kin1[8];
#pragma unroll
            for (int j = 0; j < 6; ++j) {
                st0[j] = seq0[j] + red4(accA[j]);
                st1[j] = seq1[j] + red4(accB[j]);
            }
#pragma unroll
            for (int j = 0; j < 8; ++j) { kin0[j] = red4(accA[6 + j]); kin1[j] = red4(accB[6 + j]); }

            if (g == 0) {
                int os = t * DE;
#pragma unroll
                for (int k = 0; k < DE; k += 2) {
                    *(float2*)(so0 + os + k) = make_float2(st0[k], st0[k + 1]);
                    *(float2*)(so1 + os + k) = make_float2(st1[k], st1[k + 1]);
                }
            }

#pragma unroll
            for (int j = 0; j < NIV; ++j) {
                xi0[j] = fma2(dupf(kin0[j]), NDT2, xi0[j]);
                xi1[j] = fma2(dupf(kin1[j]), NDT2, xi1[j]);
            }
        }
    }
}

extern "C" void kernel_launch(void* const* d_in, const int* in_sizes, int n_in,
                              void* d_out, int out_size) {
    const float* e    = (const float*)d_in[0];
    const float* edot = (const float*)d_in[1];
    const float* Eg   = (const float*)d_in[2];
    const float* nug  = (const float*)d_in[3];
    const float* We1  = (const float*)d_in[4];
    const float* be1  = (const float*)d_in[5];
    const float* We2  = (const float*)d_in[6];
    const float* Wd1  = (const float*)d_in[8];
    const float* bd1  = (const float*)d_in[9];
    const float* Wd2  = (const float*)d_in[10];
    const float* WE   = (const float*)d_in[12];
    const float* bE   = (const float*)d_in[13];
    const float* Wnu  = (const float*)d_in[14];
    const float* bnu  = (const float*)d_in[15];
    float* out = (float*)d_out;

    visco_kernel<<<NPAIR / 64, 128>>>(e, edot, Eg, nug, We1, be1, We2,
                                      Wd1, bd1, Wd2, WE, bE, Wnu, bnu, out);
}

// round 5
// speedup vs baseline: 1.4856x; 1.0333x over previous
#include <cuda_runtime.h>
#include <cuda_bf16.h>

#define B_TOT 32768
#define T_LEN 200
#define DE    6
#define NIV   8
#define H     128
#define DIN   46
#define NPAIR (B_TOT/2)
#define UNITS 64
#define ROWF  36
#define GRP   8
#define UPG   8          // units per group (64 row-pairs / 8 groups)
#define TD    (T_LEN*DE)
#define RUNS  (NPAIR/4)  // 4096 work quanta: 4 pairs per warp-pass

typedef unsigned long long ull;

__device__ unsigned g_run_ctr;

static __device__ __forceinline__ ull pk2(float lo, float hi) {
    ull r; asm("mov.b64 %0,{%1,%2};" : "=l"(r) : "f"(lo), "f"(hi)); return r;
}
static __device__ __forceinline__ void upk2(ull v, float& lo, float& hi) {
    asm("mov.b64 {%0,%1},%2;" : "=f"(lo), "=f"(hi) : "l"(v));
}
static __device__ __forceinline__ ull fma2(ull a, ull b, ull c) {
    ull d; asm("fma.rn.f32x2 %0,%1,%2,%3;" : "=l"(d) : "l"(a), "l"(b), "l"(c)); return d;
}
static __device__ __forceinline__ ull mul2(ull a, ull b) {
    ull d; asm("mul.rn.f32x2 %0,%1,%2;" : "=l"(d) : "l"(a), "l"(b)); return d;
}
static __device__ __forceinline__ ull add2(ull a, ull b) {
    ull d; asm("add.rn.f32x2 %0,%1,%2;" : "=l"(d) : "l"(a), "l"(b)); return d;
}
static __device__ __forceinline__ ull relu2(ull a) {
    float lo, hi; upk2(a, lo, hi);
    lo = fmaxf(lo, 0.f); hi = fmaxf(hi, 0.f);
    return pk2(lo, hi);
}
static __device__ __forceinline__ ull dupf(float v) { return pk2(v, v); }

// full reduction: packed lo+hi, then across the 8 h-groups (lane bits 2,3,4)
static __device__ __forceinline__ float red8(ull acc) {
    float lo, hi; upk2(acc, lo, hi);
    float s = lo + hi;
    s += __shfl_xor_sync(0xFFFFFFFFu, s, 4);
    s += __shfl_xor_sync(0xFFFFFFFFu, s, 8);
    s += __shfl_xor_sync(0xFFFFFFFFu, s, 16);
    return s;
}

static __device__ __forceinline__ void mlp2(const float* __restrict__ tab, int g,
    const ull* __restrict__ i6a, const ull* __restrict__ i8a, ull Ea, ull nua,
    const ull* __restrict__ i6b, const ull* __restrict__ i8b, ull Eb, ull nub,
    ull* __restrict__ accA, ull* __restrict__ accB)
{
    const int base = g * UPG;
#pragma unroll 4
    for (int i = 0; i < UPG; ++i) {
        int uu = base + ((i + g) & (UPG - 1));   // stagger: conflict-free banks
        const ulonglong2* r = reinterpret_cast<const ulonglong2*>(tab + uu * ROWF);
        ulonglong2 r0 = r[0], r1 = r[1], r2 = r[2], r3 = r[3], r4 = r[4];
        ulonglong2 r5 = r[5], r6 = r[6], r7 = r[7], r8 = r[8];

        ull pa = fma2(r7.y, Ea, r7.x);  pa = fma2(r8.x, nua, pa);
        pa = fma2(r0.x, i6a[0], pa);    pa = fma2(r0.y, i6a[1], pa);
        pa = fma2(r1.x, i6a[2], pa);    pa = fma2(r1.y, i6a[3], pa);
        pa = fma2(r2.x, i6a[4], pa);    pa = fma2(r2.y, i6a[5], pa);
        ull qa = mul2(r3.x, i8a[0]);    qa = fma2(r3.y, i8a[1], qa);
        qa = fma2(r4.x, i8a[2], qa);    qa = fma2(r4.y, i8a[3], qa);
        qa = fma2(r5.x, i8a[4], qa);    qa = fma2(r5.y, i8a[5], qa);
        qa = fma2(r6.x, i8a[6], qa);    qa = fma2(r6.y, i8a[7], qa);
        ull ra = mul2(relu2(add2(pa, qa)), r8.y);

        ull pb = fma2(r7.y, Eb, r7.x);  pb = fma2(r8.x, nub, pb);
        pb = fma2(r0.x, i6b[0], pb);    pb = fma2(r0.y, i6b[1], pb);
        pb = fma2(r1.x, i6b[2], pb);    pb = fma2(r1.y, i6b[3], pb);
        pb = fma2(r2.x, i6b[4], pb);    pb = fma2(r2.y, i6b[5], pb);
        ull qb = mul2(r3.x, i8b[0]);    qb = fma2(r3.y, i8b[1], qb);
        qb = fma2(r4.x, i8b[2], qb);    qb = fma2(r4.y, i8b[3], qb);
        qb = fma2(r5.x, i8b[4], qb);    qb = fma2(r5.y, i8b[5], qb);
        qb = fma2(r6.x, i8b[6], qb);    qb = fma2(r6.y, i8b[7], qb);
        ull rb = mul2(relu2(add2(pb, qb)), r8.y);

        accA[0]  = fma2(r0.x, ra, accA[0]);   accB[0]  = fma2(r0.x, rb, accB[0]);
        accA[1]  = fma2(r0.y, ra, accA[1]);   accB[1]  = fma2(r0.y, rb, accB[1]);
        accA[2]  = fma2(r1.x, ra, accA[2]);   accB[2]  = fma2(r1.x, rb, accB[2]);
        accA[3]  = fma2(r1.y, ra, accA[3]);   accB[3]  = fma2(r1.y, rb, accB[3]);
        accA[4]  = fma2(r2.x, ra, accA[4]);   accB[4]  = fma2(r2.x, rb, accB[4]);
        accA[5]  = fma2(r2.y, ra, accA[5]);   accB[5]  = fma2(r2.y, rb, accB[5]);
        accA[6]  = fma2(r3.x, ra, accA[6]);   accB[6]  = fma2(r3.x, rb, accB[6]);
        accA[7]  = fma2(r3.y, ra, accA[7]);   accB[7]  = fma2(r3.y, rb, accB[7]);
        accA[8]  = fma2(r4.x, ra, accA[8]);   accB[8]  = fma2(r4.x, rb, accB[8]);
        accA[9]  = fma2(r4.y, ra, accA[9]);   accB[9]  = fma2(r4.y, rb, accB[9]);
        accA[10] = fma2(r5.x, ra, accA[10]);  accB[10] = fma2(r5.x, rb, accB[10]);
        accA[11] = fma2(r5.y, ra, accA[11]);  accB[11] = fma2(r5.y, rb, accB[11]);
        accA[12] = fma2(r6.x, ra, accA[12]);  accB[12] = fma2(r6.x, rb, accB[12]);
        accA[13] = fma2(r6.y, ra, accA[13]);  accB[13] = fma2(r6.y, rb, accB[13]);
    }
}

__global__ void reset_ctr_kernel() { g_run_ctr = 0u; }

__global__ void __launch_bounds__(128, 2) visco_kernel(
    const float* __restrict__ e,   const float* __restrict__ edot,
    const float* __restrict__ Eg,  const float* __restrict__ nug,
    const float* __restrict__ We1, const float* __restrict__ be1,
    const float* __restrict__ We2,
    const float* __restrict__ Wd1, const float* __restrict__ bd1,
    const float* __restrict__ Wd2,
    const float* __restrict__ WE,  const float* __restrict__ bE,
    const float* __restrict__ Wnu, const float* __restrict__ bnu,
    float* __restrict__ out)
{
    __shared__ __align__(16) float sE2[UNITS * ROWF];
    __shared__ __align__(16) float sD2[UNITS * ROWF];

    {   // build row-pair-interleaved derived tables (thread h builds row h of both)
        int h = threadIdx.x;
        int u = h >> 1, par = h & 1;
        float* dE = sE2 + u * ROWF + par;
        float* dD = sD2 + u * ROWF + par;

        const float* w1 = We1 + h * DIN;
#pragma unroll
        for (int j = 0; j < 14; ++j) dE[2 * j] = w1[j];
        float a = be1[h], bt = 0.f, gm = 0.f;
#pragma unroll
        for (int k = 0; k < 16; ++k) { float wm = w1[14 + k]; a += wm * bE[k];  bt += wm * WE[k]; }
#pragma unroll
        for (int k = 0; k < 16; ++k) { float wm = w1[30 + k]; a += wm * bnu[k]; gm += wm * Wnu[k]; }
        dE[28] = a; dE[30] = bt; dE[32] = gm;
        dE[34] = 2.f * (We2[h] + We2[H + h]);

        const float* w2 = Wd1 + h * DIN;
#pragma unroll
        for (int j = 0; j < 14; ++j) dD[2 * j] = -w2[j];
        a = bd1[h]; bt = 0.f; gm = 0.f;
#pragma unroll
        for (int k = 0; k < 16; ++k) { float wm = w2[14 + k]; a += wm * bE[k];  bt += wm * WE[k]; }
#pragma unroll
        for (int k = 0; k < 16; ++k) { float wm = w2[30 + k]; a += wm * bnu[k]; gm += wm * Wnu[k]; }
        dD[28] = a; dD[30] = bt; dD[32] = gm;
        dD[34] = 2.f * Wd2[h];
    }
    __syncthreads();

    const int lane = threadIdx.x & 31;
    const int pr   = lane & 3;          // pair slot within warp (4 pairs/warp)
    const int g    = lane >> 2;         // h-split group 0..7
    const ull NDT2 = pk2(-0.01f, -0.01f);
    const ull SGN  = 0x8000000080000000ULL;

    for (;;) {
        // warp-level work stealing over 4096 runs (4 pairs each)
        unsigned run;
        if (lane == 0) run = atomicAdd(&g_run_ctr, 1u);
        run = __shfl_sync(0xFFFFFFFFu, run, 0);
        if (run >= RUNS) break;

        int p = (int)run * 4 + pr;
        size_t b0 = 2 * (size_t)p, b1 = b0 + 1;

        ull E0d  = dupf(Eg[b0]),  E1d  = dupf(Eg[b1]);
        ull nu0d = dupf(nug[b0]), nu1d = dupf(nug[b1]);

        const float* pe0 = e    + b0 * TD;
        const float* pe1 = pe0  + TD;
        const float* pd0 = edot + b0 * TD;
        const float* pd1 = pd0  + TD;
        float* so0 = out + b0 * TD;
        float* so1 = so0 + TD;
        float* xo0 = out + (size_t)B_TOT * TD + b0 * (size_t)(T_LEN * NIV);
        float* xo1 = xo0 + T_LEN * NIV;

        ull xi0[NIV], xi1[NIV];
#pragma unroll
        for (int j = 0; j < NIV; ++j) { xi0[j] = 0ULL; xi1[j] = 0ULL; }

        float2 ea0 = *(const float2*)(pe0), ea1 = *(const float2*)(pe0 + 2), ea2 = *(const float2*)(pe0 + 4);
        float2 eb0 = *(const float2*)(pe1), eb1 = *(const float2*)(pe1 + 2), eb2 = *(const float2*)(pe1 + 4);
        float2 da0 = *(const float2*)(pd0), da1 = *(const float2*)(pd0 + 2), da2 = *(const float2*)(pd0 + 4);
        float2 db0 = *(const float2*)(pd1), db1 = *(const float2*)(pd1 + 2), db2 = *(const float2*)(pd1 + 4);

        for (int t = 0; t < T_LEN; ++t) {
            ull et0[6] = { dupf(ea0.x), dupf(ea0.y), dupf(ea1.x), dupf(ea1.y), dupf(ea2.x), dupf(ea2.y) };
            ull et1[6] = { dupf(eb0.x), dupf(eb0.y), dupf(eb1.x), dupf(eb1.y), dupf(eb2.x), dupf(eb2.y) };
            ull ed0[6] = { dupf(da0.x) ^ SGN, dupf(da0.y) ^ SGN, dupf(da1.x) ^ SGN,
                           dupf(da1.y) ^ SGN, dupf(da2.x) ^ SGN, dupf(da2.y) ^ SGN };
            ull ed1[6] = { dupf(db0.x) ^ SGN, dupf(db0.y) ^ SGN, dupf(db1.x) ^ SGN,
                           dupf(db1.y) ^ SGN, dupf(db2.x) ^ SGN, dupf(db2.y) ^ SGN };

            if (t + 1 < T_LEN) {
                int o = (t + 1) * DE;
                ea0 = *(const float2*)(pe0 + o); ea1 = *(const float2*)(pe0 + o + 2); ea2 = *(const float2*)(pe0 + o + 4);
                eb0 = *(const float2*)(pe1 + o); eb1 = *(const float2*)(pe1 + o + 2); eb2 = *(const float2*)(pe1 + o + 4);
                da0 = *(const float2*)(pd0 + o); da1 = *(const float2*)(pd0 + o + 2); da2 = *(const float2*)(pd0 + o + 4);
                db0 = *(const float2*)(pd1 + o); db1 = *(const float2*)(pd1 + o + 2); db2 = *(const float2*)(pd1 + o + 4);
            }

            if (g == 1) {     // xi output (state entering this step)
                int ox = t * NIV;
#pragma unroll
                for (int k = 0; k < NIV; k += 2) {
                    float a0, z, a1;
                    upk2(xi0[k], a0, z); upk2(xi0[k + 1], a1, z);
                    *(float2*)(xo0 + ox + k) = make_float2(a0, a1);
                    upk2(xi1[k], a0, z); upk2(xi1[k + 1], a1, z);
                    *(float2*)(xo1 + ox + k) = make_float2(a0, a1);
                }
            }

            ull accA[14], accB[14];
#pragma unroll
            for (int j = 0; j < 14; ++j) { accA[j] = 0ULL; accB[j] = 0ULL; }
            mlp2(sE2, g, et0, xi0, E0d, nu0d, et1, xi1, E1d, nu1d, accA, accB);

            float seq0[6], seq1[6];
            ull d0[8], d1[8];
#pragma unroll
            for (int j = 0; j < 6; ++j) { seq0[j] = red8(accA[j]); seq1[j] = red8(accB[j]); }
#pragma unroll
            for (int j = 0; j < 8; ++j) { d0[j] = dupf(red8(accA[6 + j])); d1[j] = dupf(red8(accB[6 + j])); }

#pragma unroll
            for (int j = 0; j < 14; ++j) { accA[j] = 0ULL; accB[j] = 0ULL; }
            mlp2(sD2, g, ed0, d0, E0d, nu0d, ed1, d1, E1d, nu1d, accA, accB);

            // uniform reductions (all lanes participate), then divergent stores
            float st0[6], st1[6], kin0[8], kin1[8];
#pragma unroll
            for (int j = 0; j < 6; ++j) {
                st0[j] = seq0[j] + red8(accA[j]);
                st1[j] = seq1[j] + red8(accB[j]);
            }
#pragma unroll
            for (int j = 0; j < 8; ++j) { kin0[j] = red8(accA[6 + j]); kin1[j] = red8(accB[6 + j]); }

            if (g == 0) {     // stress = s_eq + (-s_neq)
                int os = t * DE;
#pragma unroll
                for (int k = 0; k < DE; k += 2) {
                    *(float2*)(so0 + os + k) = make_float2(st0[k], st0[k + 1]);
                    *(float2*)(so1 + os + k) = make_float2(st1[k], st1[k + 1]);
                }
            }

#pragma unroll
            for (int j = 0; j < NIV; ++j) {
                xi0[j] = fma2(dupf(kin0[j]), NDT2, xi0[j]);
                xi1[j] = fma2(dupf(kin1[j]), NDT2, xi1[j]);
            }
        }
    }
}

extern "C" void kernel_launch(void* const* d_in, const int* in_sizes, int n_in,
                              void* d_out, int out_size) {
    const float* e    = (const float*)d_in[0];
    const float* edot = (const float*)d_in[1];
    const float* Eg   = (const float*)d_in[2];
    const float* nug  = (const float*)d_in[3];
    const float* We1  = (const float*)d_in[4];
    const float* be1  = (const float*)d_in[5];
    const float* We2  = (const float*)d_in[6];
    const float* Wd1  = (const float*)d_in[8];
    const float* bd1  = (const float*)d_in[9];
    const float* Wd2  = (const float*)d_in[10];
    const float* WE   = (const float*)d_in[12];
    const float* bE   = (const float*)d_in[13];
    const float* Wnu  = (const float*)d_in[14];
    const float* bnu  = (const float*)d_in[15];
    float* out = (float*)d_out;

    reset_ctr_kernel<<<1, 1>>>();
    visco_kernel<<<296, 128>>>(e, edot, Eg, nug, We1, be1, We2,
                               Wd1, bd1, Wd2, WE, bE, Wnu, bnu, out);
}

// round 7
// speedup vs baseline: 1.5390x; 1.0360x over previous
#include <cuda_runtime.h>
#include <cuda_bf16.h>

#define B_TOT 32768
#define T_LEN 200
#define DE    6
#define NIV   8
#define H     128
#define DIN   46
#define NPAIR (B_TOT/2)
#define UNITS 64
#define ROWF  36
#define GRP   8
#define UPG   8          // units per group (64 row-pairs / 8 groups)
#define TD    (T_LEN*DE)
#define RUNS  (NPAIR/4)  // 4096 work quanta: 4 pairs per warp-pass

typedef unsigned long long ull;

__device__ unsigned g_run_ctr;

static __device__ __forceinline__ ull pk2(float lo, float hi) {
    ull r; asm("mov.b64 %0,{%1,%2};" : "=l"(r) : "f"(lo), "f"(hi)); return r;
}
static __device__ __forceinline__ void upk2(ull v, float& lo, float& hi) {
    asm("mov.b64 {%0,%1},%2;" : "=f"(lo), "=f"(hi) : "l"(v));
}
static __device__ __forceinline__ ull fma2(ull a, ull b, ull c) {
    ull d; asm("fma.rn.f32x2 %0,%1,%2,%3;" : "=l"(d) : "l"(a), "l"(b), "l"(c)); return d;
}
static __device__ __forceinline__ ull mul2(ull a, ull b) {
    ull d; asm("mul.rn.f32x2 %0,%1,%2;" : "=l"(d) : "l"(a), "l"(b)); return d;
}
static __device__ __forceinline__ ull add2(ull a, ull b) {
    ull d; asm("add.rn.f32x2 %0,%1,%2;" : "=l"(d) : "l"(a), "l"(b)); return d;
}
static __device__ __forceinline__ ull relu2(ull a) {
    float lo, hi; upk2(a, lo, hi);
    lo = fmaxf(lo, 0.f); hi = fmaxf(hi, 0.f);
    return pk2(lo, hi);
}
static __device__ __forceinline__ ull dupf(float v) { return pk2(v, v); }

// collapse packed (two h-rows) to a scalar per-lane partial
static __device__ __forceinline__ float hsum(ull v) {
    float lo, hi; upk2(v, lo, hi); return lo + hi;
}
// sum a scalar across the 8 h-groups (lane bits 2,3,4)
static __device__ __forceinline__ float bfly3(float s) {
    s += __shfl_xor_sync(0xFFFFFFFFu, s, 4);
    s += __shfl_xor_sync(0xFFFFFFFFu, s, 8);
    s += __shfl_xor_sync(0xFFFFFFFFu, s, 16);
    return s;
}
static __device__ __forceinline__ float red8(ull v) { return bfly3(hsum(v)); }

static __device__ __forceinline__ void mlp2(const float* __restrict__ tab, int g,
    const ull* __restrict__ i6a, const ull* __restrict__ i8a, ull Ea, ull nua,
    const ull* __restrict__ i6b, const ull* __restrict__ i8b, ull Eb, ull nub,
    ull* __restrict__ accA, ull* __restrict__ accB)
{
    const int base = g * UPG;
#pragma unroll 4
    for (int i = 0; i < UPG; ++i) {
        int uu = base + ((i + g) & (UPG - 1));   // stagger: conflict-free banks
        const ulonglong2* r = reinterpret_cast<const ulonglong2*>(tab + uu * ROWF);
        ulonglong2 r0 = r[0], r1 = r[1], r2 = r[2], r3 = r[3], r4 = r[4];
        ulonglong2 r5 = r[5], r6 = r[6], r7 = r[7], r8 = r[8];

        ull pa = fma2(r7.y, Ea, r7.x);  pa = fma2(r8.x, nua, pa);
        pa = fma2(r0.x, i6a[0], pa);    pa = fma2(r0.y, i6a[1], pa);
        pa = fma2(r1.x, i6a[2], pa);    pa = fma2(r1.y, i6a[3], pa);
        pa = fma2(r2.x, i6a[4], pa);    pa = fma2(r2.y, i6a[5], pa);
        ull qa = mul2(r3.x, i8a[0]);    qa = fma2(r3.y, i8a[1], qa);
        qa = fma2(r4.x, i8a[2], qa);    qa = fma2(r4.y, i8a[3], qa);
        qa = fma2(r5.x, i8a[4], qa);    qa = fma2(r5.y, i8a[5], qa);
        qa = fma2(r6.x, i8a[6], qa);    qa = fma2(r6.y, i8a[7], qa);
        ull ra = mul2(relu2(add2(pa, qa)), r8.y);

        ull pb = fma2(r7.y, Eb, r7.x);  pb = fma2(r8.x, nub, pb);
        pb = fma2(r0.x, i6b[0], pb);    pb = fma2(r0.y, i6b[1], pb);
        pb = fma2(r1.x, i6b[2], pb);    pb = fma2(r1.y, i6b[3], pb);
        pb = fma2(r2.x, i6b[4], pb);    pb = fma2(r2.y, i6b[5], pb);
        ull qb = mul2(r3.x, i8b[0]);    qb = fma2(r3.y, i8b[1], qb);
        qb = fma2(r4.x, i8b[2], qb);    qb = fma2(r4.y, i8b[3], qb);
        qb = fma2(r5.x, i8b[4], qb);    qb = fma2(r5.y, i8b[5], qb);
        qb = fma2(r6.x, i8b[6], qb);    qb = fma2(r6.y, i8b[7], qb);
        ull rb = mul2(relu2(add2(pb, qb)), r8.y);

        accA[0]  = fma2(r0.x, ra, accA[0]);   accB[0]  = fma2(r0.x, rb, accB[0]);
        accA[1]  = fma2(r0.y, ra, accA[1]);   accB[1]  = fma2(r0.y, rb, accB[1]);
        accA[2]  = fma2(r1.x, ra, accA[2]);   accB[2]  = fma2(r1.x, rb, accB[2]);
        accA[3]  = fma2(r1.y, ra, accA[3]);   accB[3]  = fma2(r1.y, rb, accB[3]);
        accA[4]  = fma2(r2.x, ra, accA[4]);   accB[4]  = fma2(r2.x, rb, accB[4]);
        accA[5]  = fma2(r2.y, ra, accA[5]);   accB[5]  = fma2(r2.y, rb, accB[5]);
        accA[6]  = fma2(r3.x, ra, accA[6]);   accB[6]  = fma2(r3.x, rb, accB[6]);
        accA[7]  = fma2(r3.y, ra, accA[7]);   accB[7]  = fma2(r3.y, rb, accB[7]);
        accA[8]  = fma2(r4.x, ra, accA[8]);   accB[8]  = fma2(r4.x, rb, accB[8]);
        accA[9]  = fma2(r4.y, ra, accA[9]);   accB[9]  = fma2(r4.y, rb, accB[9]);
        accA[10] = fma2(r5.x, ra, accA[10]);  accB[10] = fma2(r5.x, rb, accB[10]);
        accA[11] = fma2(r5.y, ra, accA[11]);  accB[11] = fma2(r5.y, rb, accB[11]);
        accA[12] = fma2(r6.x, ra, accA[12]);  accB[12] = fma2(r6.x, rb, accB[12]);
        accA[13] = fma2(r6.y, ra, accA[13]);  accB[13] = fma2(r6.y, rb, accB[13]);
    }
}

__global__ void reset_ctr_kernel() { g_run_ctr = 0u; }

__global__ void __launch_bounds__(128, 2) visco_kernel(
    const float* __restrict__ e,   const float* __restrict__ edot,
    const float* __restrict__ Eg,  const float* __restrict__ nug,
    const float* __restrict__ We1, const float* __restrict__ be1,
    const float* __restrict__ We2,
    const float* __restrict__ Wd1, const float* __restrict__ bd1,
    const float* __restrict__ Wd2,
    const float* __restrict__ WE,  const float* __restrict__ bE,
    const float* __restrict__ Wnu, const float* __restrict__ bnu,
    float* __restrict__ out)
{
    __shared__ __align__(16) float sE2[UNITS * ROWF];
    __shared__ __align__(16) float sD2[UNITS * ROWF];

    {   // build row-pair-interleaved derived tables (thread h builds row h of both)
        int h = threadIdx.x;
        int u = h >> 1, par = h & 1;
        float* dE = sE2 + u * ROWF + par;
        float* dD = sD2 + u * ROWF + par;

        const float* w1 = We1 + h * DIN;
#pragma unroll
        for (int j = 0; j < 14; ++j) dE[2 * j] = w1[j];
        float a = be1[h], bt = 0.f, gm = 0.f;
#pragma unroll
        for (int k = 0; k < 16; ++k) { float wm = w1[14 + k]; a += wm * bE[k];  bt += wm * WE[k]; }
#pragma unroll
        for (int k = 0; k < 16; ++k) { float wm = w1[30 + k]; a += wm * bnu[k]; gm += wm * Wnu[k]; }
        dE[28] = a; dE[30] = bt; dE[32] = gm;
        dE[34] = 2.f * (We2[h] + We2[H + h]);

        const float* w2 = Wd1 + h * DIN;
#pragma unroll
        for (int j = 0; j < 14; ++j) dD[2 * j] = -w2[j];
        a = bd1[h]; bt = 0.f; gm = 0.f;
#pragma unroll
        for (int k = 0; k < 16; ++k) { float wm = w2[14 + k]; a += wm * bE[k];  bt += wm * WE[k]; }
#pragma unroll
        for (int k = 0; k < 16; ++k) { float wm = w2[30 + k]; a += wm * bnu[k]; gm += wm * Wnu[k]; }
        dD[28] = a; dD[30] = bt; dD[32] = gm;
        dD[34] = 2.f * Wd2[h];
    }
    __syncthreads();

    const int lane = threadIdx.x & 31;
    const int pr   = lane & 3;                   // pair slot within warp
    const int g    = lane >> 2;                  // h-split group 0..7
    const ull NDT2 = pk2(-0.01f, -0.01f);
    const ull SGN  = 0x8000000080000000ULL;

    for (;;) {
        unsigned run;
        if (lane == 0) run = atomicAdd(&g_run_ctr, 1u);
        run = __shfl_sync(0xFFFFFFFFu, run, 0);
        if (run >= RUNS) break;

        int p = (int)run * 4 + pr;
        size_t b0 = 2 * (size_t)p, b1 = b0 + 1;

        ull E0d  = dupf(Eg[b0]),  E1d  = dupf(Eg[b1]);
        ull nu0d = dupf(nug[b0]), nu1d = dupf(nug[b1]);

        const float* pe0 = e    + b0 * TD;
        const float* pe1 = pe0  + TD;
        const float* pd0 = edot + b0 * TD;
        const float* pd1 = pd0  + TD;
        float* so0 = out + b0 * TD;
        float* so1 = so0 + TD;
        float* xo0 = out + (size_t)B_TOT * TD + b0 * (size_t)(T_LEN * NIV);
        float* xo1 = xo0 + T_LEN * NIV;

        ull xi0[NIV], xi1[NIV];
#pragma unroll
        for (int j = 0; j < NIV; ++j) { xi0[j] = 0ULL; xi1[j] = 0ULL; }

        float2 ea0 = *(const float2*)(pe0), ea1 = *(const float2*)(pe0 + 2), ea2 = *(const float2*)(pe0 + 4);
        float2 eb0 = *(const float2*)(pe1), eb1 = *(const float2*)(pe1 + 2), eb2 = *(const float2*)(pe1 + 4);
        float2 da0 = *(const float2*)(pd0), da1 = *(const float2*)(pd0 + 2), da2 = *(const float2*)(pd0 + 4);
        float2 db0 = *(const float2*)(pd1), db1 = *(const float2*)(pd1 + 2), db2 = *(const float2*)(pd1 + 4);

        for (int t = 0; t < T_LEN; ++t) {
            ull et0[6] = { dupf(ea0.x), dupf(ea0.y), dupf(ea1.x), dupf(ea1.y), dupf(ea2.x), dupf(ea2.y) };
            ull et1[6] = { dupf(eb0.x), dupf(eb0.y), dupf(eb1.x), dupf(eb1.y), dupf(eb2.x), dupf(eb2.y) };
            ull ed0[6] = { dupf(da0.x) ^ SGN, dupf(da0.y) ^ SGN, dupf(da1.x) ^ SGN,
                           dupf(da1.y) ^ SGN, dupf(da2.x) ^ SGN, dupf(da2.y) ^ SGN };
            ull ed1[6] = { dupf(db0.x) ^ SGN, dupf(db0.y) ^ SGN, dupf(db1.x) ^ SGN,
                           dupf(db1.y) ^ SGN, dupf(db2.x) ^ SGN, dupf(db2.y) ^ SGN };

            if (t + 1 < T_LEN) {
                int o = (t + 1) * DE;
                ea0 = *(const float2*)(pe0 + o); ea1 = *(const float2*)(pe0 + o + 2); ea2 = *(const float2*)(pe0 + o + 4);
                eb0 = *(const float2*)(pe1 + o); eb1 = *(const float2*)(pe1 + o + 2); eb2 = *(const float2*)(pe1 + o + 4);
                da0 = *(const float2*)(pd0 + o); da1 = *(const float2*)(pd0 + o + 2); da2 = *(const float2*)(pd0 + o + 4);
                db0 = *(const float2*)(pd1 + o); db1 = *(const float2*)(pd1 + o + 2); db2 = *(const float2*)(pd1 + o + 4);
            }

            if (g == 1) {     // xi output (state entering this step)
                int ox = t * NIV;
#pragma unroll
                for (int k = 0; k < NIV; k += 2) {
                    float a0, z, a1;
                    upk2(xi0[k], a0, z); upk2(xi0[k + 1], a1, z);
                    *(float2*)(xo0 + ox + k) = make_float2(a0, a1);
                    upk2(xi1[k], a0, z); upk2(xi1[k + 1], a1, z);
                    *(float2*)(xo1 + ox + k) = make_float2(a0, a1);
                }
            }

            ull accA[14], accB[14];
#pragma unroll
            for (int j = 0; j < 14; ++j) { accA[j] = 0ULL; accB[j] = 0ULL; }
            mlp2(sE2, g, et0, xi0, E0d, nu0d, et1, xi1, E1d, nu1d, accA, accB);

            // seq: collapse to per-lane scalar partials only (no shuffles yet);
            // d: full reduce + broadcast (needed as D-MLP input in all lanes)
            float hE0[6], hE1[6];
            ull d0[8], d1[8];
#pragma unroll
            for (int j = 0; j < 6; ++j) { hE0[j] = hsum(accA[j]); hE1[j] = hsum(accB[j]); }
#pragma unroll
            for (int j = 0; j < 8; ++j) { d0[j] = dupf(red8(accA[6 + j])); d1[j] = dupf(red8(accB[6 + j])); }

#pragma unroll
            for (int j = 0; j < 14; ++j) { accA[j] = 0ULL; accB[j] = 0ULL; }
            mlp2(sD2, g, ed0, d0, E0d, nu0d, ed1, d1, E1d, nu1d, accA, accB);

            // stress: single butterfly over combined E+D partials (saves 12 butterflies)
            float st0[6], st1[6], kin0[8], kin1[8];
#pragma unroll
            for (int j = 0; j < 6; ++j) {
                st0[j] = bfly3(hE0[j] + hsum(accA[j]));
                st1[j] = bfly3(hE1[j] + hsum(accB[j]));
            }
#pragma unroll
            for (int j = 0; j < 8; ++j) { kin0[j] = red8(accA[6 + j]); kin1[j] = red8(accB[6 + j]); }

            if (g == 0) {     // stress = s_eq + (-s_neq)
                int os = t * DE;
#pragma unroll
                for (int k = 0; k < DE; k += 2) {
                    *(float2*)(so0 + os + k) = make_float2(st0[k], st0[k + 1]);
                    *(float2*)(so1 + os + k) = make_float2(st1[k], st1[k + 1]);
                }
            }

#pragma unroll
            for (int j = 0; j < NIV; ++j) {
                xi0[j] = fma2(dupf(kin0[j]), NDT2, xi0[j]);
                xi1[j] = fma2(dupf(kin1[j]), NDT2, xi1[j]);
            }
        }
    }
}

extern "C" void kernel_launch(void* const* d_in, const int* in_sizes, int n_in,
                              void* d_out, int out_size) {
    const float* e    = (const float*)d_in[0];
    const float* edot = (const float*)d_in[1];
    const float* Eg   = (const float*)d_in[2];
    const float* nug  = (const float*)d_in[3];
    const float* We1  = (const float*)d_in[4];
    const float* be1  = (const float*)d_in[5];
    const float* We2  = (const float*)d_in[6];
    const float* Wd1  = (const float*)d_in[8];
    const float* bd1  = (const float*)d_in[9];
    const float* Wd2  = (const float*)d_in[10];
    const float* WE   = (const float*)d_in[12];
    const float* bE   = (const float*)d_in[13];
    const float* Wnu  = (const float*)d_in[14];
    const float* bnu  = (const float*)d_in[15];
    float* out = (float*)d_out;

    reset_ctr_kernel<<<1, 1>>>();
    visco_kernel<<<296, 128>>>(e, edot, Eg, nug, We1, be1, We2,
                               Wd1, bd1, Wd2, WE, bE, Wnu, bnu, out);
}